// round 7
// baseline (speedup 1.0000x reference)
#include <cuda_runtime.h>
#include <math.h>

#define SEQ   512
#define BATCH 32
#define ROWS  16384        // BATCH*SEQ
#define HID   300
#define HDIM  64
#define NH    8
#define DH    8
#define NL    6
#define FF    1200
#define NC    1000

// ---------------- scratch (static device globals; no allocation) ----------------
__device__ float g_acc [ROWS*HID];
__device__ float g_out [ROWS*HID];
__device__ float g_xa  [ROWS*HID];
__device__ float g_tmp [ROWS*HID];
__device__ float g_q   [ROWS*HDIM];
__device__ float g_k   [ROWS*HDIM];
__device__ float g_v   [ROWS*HDIM];
__device__ float g_qh  [ROWS*HDIM];
__device__ float g_kh  [ROWS*HDIM];
__device__ float g_vh  [ROWS*HDIM];
__device__ float g_attn[ROWS*HDIM];
__device__ float g_ffh [ROWS*FF];
__device__ float g_pe  [SEQ*HID];
__device__ float g_part[8*BATCH*HID];
__device__ float g_sums[BATCH*HID];
__device__ float g_logits[BATCH*NC];

// ---------------- positional encoding table ----------------
__global__ void pe_kernel(float* __restrict__ pe) {
    int s = blockIdx.x;
    for (int c = threadIdx.x; c < HID; c += blockDim.x) {
        double expo = (double)(c & ~1) / (double)HID;
        double ang  = (double)s * exp(-expo * 9.210340371976182736); // ln(10000)
        pe[s*HID + c] = (c & 1) ? (float)cos(ang) : (float)sin(ang);
    }
}

// acc = 2*emb[token] + PE   (x2 = emb+PE; acc = x2 + x1)
__global__ void embed_kernel(const int* __restrict__ tok,
                             const float* __restrict__ emb,
                             const float* __restrict__ pe,
                             float* __restrict__ accb) {
    int row = blockIdx.x;
    int s   = row & (SEQ - 1);
    long long t = tok[row];
    const float* er = emb + t * HID;
    const float* pr = pe + s * HID;
    for (int c = threadIdx.x; c < HID; c += blockDim.x) {
        accb[row*HID + c] = 2.f * er[c] + pr[c];
    }
}

// ================= tf32 tensor-core GEMM, cp.async double-buffered =================

__device__ __forceinline__ void mma_tf32(float d[4], const unsigned a[4],
                                         const unsigned b[2], const float c[4]) {
    asm volatile(
        "mma.sync.aligned.m16n8k8.row.col.f32.tf32.tf32.f32 "
        "{%0,%1,%2,%3}, {%4,%5,%6,%7}, {%8,%9}, {%10,%11,%12,%13};\n"
        : "=f"(d[0]), "=f"(d[1]), "=f"(d[2]), "=f"(d[3])
        : "r"(a[0]), "r"(a[1]), "r"(a[2]), "r"(a[3]),
          "r"(b[0]), "r"(b[1]),
          "f"(c[0]), "f"(c[1]), "f"(c[2]), "f"(c[3]));
}

__device__ __forceinline__ void cp16(void* smem, const void* gmem) {
    unsigned saddr = (unsigned)__cvta_generic_to_shared(smem);
    asm volatile("cp.async.cg.shared.global [%0], [%1], 16;" :: "r"(saddr), "l"(gmem));
}

#define AS_LD 20    // 128x16 A tile, m-major rows padded to 20 floats

template<int BN, bool RELU, bool BIAS, bool RES>
__device__ __forceinline__ void gemm_body(const float* __restrict__ A,
                                          const float* __restrict__ B,
                                          const float* __restrict__ bias,
                                          const float* __restrict__ res,
                                          float* __restrict__ C,
                                          int N, int K, int bm, int bn) {
    constexpr int BS_LD = BN + 8;     // %32 == 8 -> conflict-free
    constexpr int NT = BN / 16;       // n-tiles of 8 per warp
    __shared__ float As[2][128][AS_LD];
    __shared__ float Bs[2][16][BS_LD];

    const int tid  = threadIdx.x;
    const int lane = tid & 31, warp = tid >> 5;
    const int gid  = lane >> 2, tig = lane & 3;
    const int rowb = (warp & 3) * 32;          // 4 warps over M
    const int nb   = (warp >> 2) * (BN / 2);   // 2 warps over N

    float acc[2][NT][4];
#pragma unroll
    for (int mt = 0; mt < 2; mt++)
#pragma unroll
        for (int nt = 0; nt < NT; nt++)
#pragma unroll
            for (int i = 0; i < 4; i++) acc[mt][nt][i] = 0.f;

    const int S = (K + 15) / 16;

    auto issue = [&](int s, int buf) {
        int k0 = s * 16;
#pragma unroll
        for (int j = 0; j < 2; j++) {
            int idx = tid + j * 256;
            int r = idx >> 2, c4 = (idx & 3) * 4;
            float* dst = &As[buf][r][c4];
            if (k0 + c4 < K) cp16(dst, A + (size_t)(bm + r) * K + k0 + c4);
            else *(float4*)dst = make_float4(0.f, 0.f, 0.f, 0.f);
        }
#pragma unroll
        for (int j = 0; j < BN / 64; j++) {
            int idx = tid + j * 256;
            int r = idx / (BN / 4);
            int c4 = (idx % (BN / 4)) * 4;
            float* dst = &Bs[buf][r][c4];
            int gr = k0 + r, gc = bn + c4;
            if (gr < K && gc < N) cp16(dst, B + (size_t)gr * N + gc);
            else *(float4*)dst = make_float4(0.f, 0.f, 0.f, 0.f);
        }
        asm volatile("cp.async.commit_group;");
    };

    issue(0, 0);

    for (int s = 0; s < S; s++) {
        asm volatile("cp.async.wait_group 0;");
        __syncthreads();
        if (s + 1 < S) issue(s + 1, (s + 1) & 1);

        const float (*as)[AS_LD] = As[s & 1];
        const float (*bs)[BS_LD] = Bs[s & 1];
#pragma unroll
        for (int ks = 0; ks < 2; ks++) {
            const int kk = ks * 8;
            unsigned af[2][4], bf[NT][2];
#pragma unroll
            for (int mt = 0; mt < 2; mt++) {
                int r0 = rowb + mt * 16 + gid;
                af[mt][0] = __float_as_uint(as[r0    ][kk + tig    ]);
                af[mt][1] = __float_as_uint(as[r0 + 8][kk + tig    ]);
                af[mt][2] = __float_as_uint(as[r0    ][kk + tig + 4]);
                af[mt][3] = __float_as_uint(as[r0 + 8][kk + tig + 4]);
            }
#pragma unroll
            for (int nt = 0; nt < NT; nt++) {
                int c0 = nb + nt * 8 + gid;
                bf[nt][0] = __float_as_uint(bs[kk + tig    ][c0]);
                bf[nt][1] = __float_as_uint(bs[kk + tig + 4][c0]);
            }
#pragma unroll
            for (int mt = 0; mt < 2; mt++)
#pragma unroll
                for (int nt = 0; nt < NT; nt++)
                    mma_tf32(acc[mt][nt], af[mt], bf[nt], acc[mt][nt]);
        }
    }

    // epilogue
#pragma unroll
    for (int mt = 0; mt < 2; mt++) {
        int row0 = bm + rowb + mt * 16 + gid;
#pragma unroll
        for (int nt = 0; nt < NT; nt++) {
            int col = bn + nb + nt * 8 + 2 * tig;
#pragma unroll
            for (int half = 0; half < 2; half++) {
                int row = row0 + half * 8;
                float v0 = acc[mt][nt][half * 2 + 0];
                float v1 = acc[mt][nt][half * 2 + 1];
                if (col < N) {
                    if (BIAS) v0 += bias[col];
                    if (RES)  v0 += res[(size_t)row * N + col];
                    if (RELU) v0 = fmaxf(v0, 0.f);
                    C[(size_t)row * N + col] = v0;
                }
                if (col + 1 < N) {
                    if (BIAS) v1 += bias[col + 1];
                    if (RES)  v1 += res[(size_t)row * N + col + 1];
                    if (RELU) v1 = fmaxf(v1, 0.f);
                    C[(size_t)row * N + col + 1] = v1;
                }
            }
        }
    }
}

template<int BN, bool RELU, bool BIAS, bool RES>
__global__ void __launch_bounds__(256) gemm_tc(const float* __restrict__ A,
                                               const float* __restrict__ B,
                                               const float* __restrict__ bias,
                                               const float* __restrict__ res,
                                               float* __restrict__ C,
                                               int N, int K) {
    gemm_body<BN, RELU, BIAS, RES>(A, B, bias, res, C, N, K,
                                   blockIdx.y * 128, blockIdx.x * BN);
}

// fused QKV: grid (1, M/128, 3)
__global__ void __launch_bounds__(256) qkv_tc(const float* __restrict__ A,
                                              const float* __restrict__ WQa,
                                              const float* __restrict__ WKa,
                                              const float* __restrict__ WVa,
                                              float* __restrict__ Q,
                                              float* __restrict__ Kk,
                                              float* __restrict__ V) {
    const float* B = (blockIdx.z == 0) ? WQa : (blockIdx.z == 1) ? WKa : WVa;
    float* C = (blockIdx.z == 0) ? Q : (blockIdx.z == 1) ? Kk : V;
    gemm_body<64, false, false, false>(A, B, nullptr, nullptr, C, HDIM, HID,
                                       blockIdx.y * 128, 0);
}

// ---------------- reorg: [row][d*8+h] -> head-major [h][row][d] (coalesced both sides) ----------------
__global__ void __launch_bounds__(256) reorg3(const float* __restrict__ q,
                                              const float* __restrict__ k,
                                              const float* __restrict__ v,
                                              float* __restrict__ qh,
                                              float* __restrict__ kh,
                                              float* __restrict__ vh) {
    const float* in  = (blockIdx.y == 0) ? q : (blockIdx.y == 1) ? k : v;
    float*       out = (blockIdx.y == 0) ? qh : (blockIdx.y == 1) ? kh : vh;
    __shared__ float s[64][65];
    const int base = blockIdx.x * 64;
    const int tid = threadIdx.x;
#pragma unroll
    for (int i = 0; i < 16; i++) {
        int idx = tid + i * 256;
        int r = idx >> 6, c = idx & 63;
        s[r][c] = in[(size_t)(base + r) * 64 + c];
    }
    __syncthreads();
#pragma unroll
    for (int i = 0; i < 16; i++) {
        int idx = tid + i * 256;
        int d = idx & 7, r = (idx >> 3) & 63, h = idx >> 9;
        out[((size_t)h * ROWS + base + r) * 8 + d] = s[r][d * 8 + h];
    }
}

// ---------------- attention: split-K2, head-major inputs ----------------
// grid (NH, BATCH, 4): block = 128 queries x 2 key-halves, 256 threads
__global__ void __launch_bounds__(256) attn_kernel(const float* __restrict__ Qh,
                                                   const float* __restrict__ Kh,
                                                   const float* __restrict__ Vh,
                                                   const int* __restrict__ tok,
                                                   float* __restrict__ O) {
    const int h = blockIdx.x;
    const int b = blockIdx.y;
    const int base = b * SEQ;
    __shared__ float Ks[SEQ][8];
    __shared__ float Vs[SEQ][8];
    __shared__ float mmul[SEQ];
    __shared__ float red[128][10];
    const int tid = threadIdx.x;

    const float4* kp = (const float4*)(Kh + ((size_t)h * ROWS + base) * 8);
    const float4* vp = (const float4*)(Vh + ((size_t)h * ROWS + base) * 8);
    float4* Ks4 = (float4*)Ks;
    float4* Vs4 = (float4*)Vs;
#pragma unroll
    for (int i = 0; i < 4; i++) {
        int idx = tid + i * 256;       // 1024 float4 per tensor
        Ks4[idx] = kp[idx];
        Vs4[idx] = vp[idx];
    }
#pragma unroll
    for (int i = 0; i < 2; i++) {
        int idx = tid + i * 256;
        mmul[idx] = (tok[base + idx] == 0) ? 0.f : 1.f;
    }
    __syncthreads();

    const int ql = tid & 127;
    const int kh2 = tid >> 7;                 // key half 0/1
    const int qi = blockIdx.z * 128 + ql;
    const float scale = 0.05773502691896258f; // 1/sqrt(300)

    float q[8];
    const float* qp = Qh + ((size_t)h * ROWS + base + qi) * 8;
    {
        float4 q0 = *(const float4*)qp;
        float4 q1 = *(const float4*)(qp + 4);
        q[0] = q0.x * scale; q[1] = q0.y * scale; q[2] = q0.z * scale; q[3] = q0.w * scale;
        q[4] = q1.x * scale; q[5] = q1.y * scale; q[6] = q1.z * scale; q[7] = q1.w * scale;
    }

    float ssum = 0.f, o[8];
#pragma unroll
    for (int d = 0; d < 8; d++) o[d] = 0.f;

    const int k0 = kh2 * 256;
#pragma unroll 4
    for (int k = k0; k < k0 + 256; k++) {
        float4 kk0 = *(const float4*)&Ks[k][0];
        float4 kk1 = *(const float4*)&Ks[k][4];
        float s = q[0]*kk0.x + q[1]*kk0.y + q[2]*kk0.z + q[3]*kk0.w
                + q[4]*kk1.x + q[5]*kk1.y + q[6]*kk1.z + q[7]*kk1.w;
        float p = __expf(s) * mmul[k];
        ssum += p;
        float4 v0 = *(const float4*)&Vs[k][0];
        float4 v1 = *(const float4*)&Vs[k][4];
        o[0] += p * v0.x; o[1] += p * v0.y; o[2] += p * v0.z; o[3] += p * v0.w;
        o[4] += p * v1.x; o[5] += p * v1.y; o[6] += p * v1.z; o[7] += p * v1.w;
    }

    if (kh2 == 1) {
        red[ql][0] = ssum;
#pragma unroll
        for (int d = 0; d < 8; d++) red[ql][1 + d] = o[d];
    }
    __syncthreads();
    if (kh2 == 0) {
        ssum += red[ql][0];
#pragma unroll
        for (int d = 0; d < 8; d++) o[d] += red[ql][1 + d];
        float inv = 1.f / ssum;
        float* op = O + (size_t)(base + qi) * HDIM + h * 8;   // head-major concat
        float4 r0 = make_float4(o[0]*inv, o[1]*inv, o[2]*inv, o[3]*inv);
        float4 r1 = make_float4(o[4]*inv, o[5]*inv, o[6]*inv, o[7]*inv);
        *(float4*)op = r0;
        *(float4*)(op + 4) = r1;
    }
}

// ---------------- LayerNorm: warp per row, shuffle reductions ----------------
template<bool ACC>
__global__ void __launch_bounds__(256) ln_kernel(const float* __restrict__ in,
                                                 float* __restrict__ outp,
                                                 const float* __restrict__ g,
                                                 const float* __restrict__ bt,
                                                 float* __restrict__ accb) {
    const int warp = threadIdx.x >> 5, lane = threadIdx.x & 31;
    const int row = blockIdx.x * 8 + warp;
    const float* x = in + (size_t)row * HID;

    float v[10];
    float s = 0.f;
#pragma unroll
    for (int i = 0; i < 10; i++) {
        int c = lane + i * 32;
        v[i] = (c < HID) ? x[c] : 0.f;
        s += v[i];
    }
#pragma unroll
    for (int o = 16; o; o >>= 1) s += __shfl_xor_sync(0xffffffffu, s, o);
    float mu = s / HID;

    float sq = 0.f;
#pragma unroll
    for (int i = 0; i < 10; i++) {
        int c = lane + i * 32;
        if (c < HID) { float d = v[i] - mu; sq += d * d; }
    }
#pragma unroll
    for (int o = 16; o; o >>= 1) sq += __shfl_xor_sync(0xffffffffu, sq, o);
    float inv = rsqrtf(sq / (HID - 1) + 1e-8f);

    float gg = g[0], bb = bt[0];
#pragma unroll
    for (int i = 0; i < 10; i++) {
        int c = lane + i * 32;
        if (c < HID) {
            float y = gg * (v[i] - mu) * inv + bb;
            outp[(size_t)row * HID + c] = y;
            if (ACC) accb[(size_t)row * HID + c] += y;
        }
    }
}

// ---------------- sum over sequence, two-stage (deterministic) ----------------
__global__ void seqsum1(const float* __restrict__ in, float* __restrict__ part) {
    int b = blockIdx.x, ch = blockIdx.y, c = threadIdx.x;
    if (c < HID) {
        float a = 0.f;
        const float* p = in + ((size_t)b * SEQ + ch * 64) * HID + c;
        for (int s = 0; s < 64; s++) a += p[(size_t)s * HID];
        part[((size_t)ch * BATCH + b) * HID + c] = a;
    }
}
__global__ void seqsum2(const float* __restrict__ part, float* __restrict__ sums) {
    int b = blockIdx.x, c = threadIdx.x;
    if (c < HID) {
        float a = 0.f;
#pragma unroll
        for (int ch = 0; ch < 8; ch++) a += part[((size_t)ch * BATCH + b) * HID + c];
        sums[b * HID + c] = a;
    }
}

// ---------------- classifier: (B,HID) @ (HID,NC) ----------------
__global__ void classify_kernel(const float* __restrict__ sums, const float* __restrict__ Vd,
                                float* __restrict__ logits) {
    int b = blockIdx.y;
    int c = blockIdx.x * 256 + threadIdx.x;
    __shared__ float srow[HID];
    for (int i = threadIdx.x; i < HID; i += 256) srow[i] = sums[b * HID + i];
    __syncthreads();
    if (c < NC) {
        float a = 0.f;
        for (int k = 0; k < HID; k++) a += srow[k] * Vd[(size_t)k * NC + c];
        logits[b * NC + c] = a;
    }
}

// ---------------- final LN (ddof=1) + softmax over NC ----------------
__global__ void final_kernel(const float* __restrict__ logits,
                             const float* __restrict__ gf, const float* __restrict__ bf,
                             float* __restrict__ outp) {
    const int b = blockIdx.x;
    const int t = threadIdx.x;   // 256
    __shared__ float buf[NC];
    __shared__ float red[256];
    const float* x = logits + (size_t)b * NC;

    float s = 0.f;
    for (int c = t; c < NC; c += 256) { float v = x[c]; buf[c] = v; s += v; }
    red[t] = s; __syncthreads();
    for (int st = 128; st > 0; st >>= 1) { if (t < st) red[t] += red[t + st]; __syncthreads(); }
    float mu = red[0] / NC;
    __syncthreads();

    float sq = 0.f;
    for (int c = t; c < NC; c += 256) { float d = buf[c] - mu; sq += d * d; }
    red[t] = sq; __syncthreads();
    for (int st = 128; st > 0; st >>= 1) { if (t < st) red[t] += red[t + st]; __syncthreads(); }
    float inv = rsqrtf(red[0] / (NC - 1) + 1e-8f);
    float gg = gf[0], bb = bf[0];
    __syncthreads();

    for (int c = t; c < NC; c += 256) buf[c] = gg * (buf[c] - mu) * inv + bb;
    __syncthreads();

    float mx = -1e30f;
    for (int c = t; c < NC; c += 256) mx = fmaxf(mx, buf[c]);
    red[t] = mx; __syncthreads();
    for (int st = 128; st > 0; st >>= 1) { if (t < st) red[t] = fmaxf(red[t], red[t + st]); __syncthreads(); }
    float rmax = red[0];
    __syncthreads();

    float es = 0.f;
    for (int c = t; c < NC; c += 256) es += __expf(buf[c] - rmax);
    red[t] = es; __syncthreads();
    for (int st = 128; st > 0; st >>= 1) { if (t < st) red[t] += red[t + st]; __syncthreads(); }
    float invs = 1.f / red[0];
    __syncthreads();

    for (int c = t; c < NC; c += 256) outp[(size_t)b * NC + c] = __expf(buf[c] - rmax) * invs;
}

// ---------------- launch ----------------
extern "C" void kernel_launch(void* const* d_in, const int* in_sizes, int n_in,
                              void* d_out, int out_size) {
    const int*   xk  = (const int*)  d_in[0];
    const float* emb = (const float*)d_in[1];
    const float* WQ  = (const float*)d_in[2];
    const float* WK  = (const float*)d_in[3];
    const float* WV  = (const float*)d_in[4];
    const float* WO  = (const float*)d_in[5];
    const float* W1  = (const float*)d_in[6];
    const float* b1  = (const float*)d_in[7];
    const float* W2  = (const float*)d_in[8];
    const float* b2  = (const float*)d_in[9];
    const float* g1  = (const float*)d_in[10];
    const float* be1 = (const float*)d_in[11];
    const float* g2  = (const float*)d_in[12];
    const float* be2 = (const float*)d_in[13];
    const float* Vd  = (const float*)d_in[14];
    const float* gf  = (const float*)d_in[15];
    const float* bf  = (const float*)d_in[16];
    float* outp = (float*)d_out;

    float *acc, *outb, *xa, *tmp, *q, *k, *v, *qh, *kh, *vh, *attn, *ffh, *pe, *part, *sums, *logits;
    cudaGetSymbolAddress((void**)&acc,   g_acc);
    cudaGetSymbolAddress((void**)&outb,  g_out);
    cudaGetSymbolAddress((void**)&xa,    g_xa);
    cudaGetSymbolAddress((void**)&tmp,   g_tmp);
    cudaGetSymbolAddress((void**)&q,     g_q);
    cudaGetSymbolAddress((void**)&k,     g_k);
    cudaGetSymbolAddress((void**)&v,     g_v);
    cudaGetSymbolAddress((void**)&qh,    g_qh);
    cudaGetSymbolAddress((void**)&kh,    g_kh);
    cudaGetSymbolAddress((void**)&vh,    g_vh);
    cudaGetSymbolAddress((void**)&attn,  g_attn);
    cudaGetSymbolAddress((void**)&ffh,   g_ffh);
    cudaGetSymbolAddress((void**)&pe,    g_pe);
    cudaGetSymbolAddress((void**)&part,  g_part);
    cudaGetSymbolAddress((void**)&sums,  g_sums);
    cudaGetSymbolAddress((void**)&logits,g_logits);

    pe_kernel<<<SEQ, 128>>>(pe);
    embed_kernel<<<ROWS, 128>>>(xk, emb, pe, acc);

    const int MB = ROWS / 128;   // 128 m-blocks

    for (int l = 0; l < NL; l++) {
        const float* wq = WQ + (size_t)l * HID * HDIM;
        const float* wk = WK + (size_t)l * HID * HDIM;
        const float* wv = WV + (size_t)l * HID * HDIM;
        const float* wo = WO + (size_t)l * HDIM * HID;
        const float* w1 = W1 + (size_t)l * HID * FF;
        const float* w2 = W2 + (size_t)l * FF * HID;
        const float* bb1 = b1 + (size_t)l * FF;
        const float* bb2 = b2 + (size_t)l * HID;

        qkv_tc<<<dim3(1, MB, 3), 256>>>(acc, wq, wk, wv, q, k, v);
        reorg3<<<dim3(ROWS / 64, 3), 256>>>(q, k, v, qh, kh, vh);

        attn_kernel<<<dim3(NH, BATCH, 4), 256>>>(qh, kh, vh, xk, attn);

        dim3 go((HID + 63) / 64, MB);
        gemm_tc<64, false,false,true><<<go, 256>>>(attn, wo, nullptr, acc, tmp, HID, HDIM);
        ln_kernel<false><<<ROWS/8, 256>>>(tmp, xa, g1 + l, be1 + l, nullptr);

        dim3 gf1((FF + 127) / 128, MB);
        gemm_tc<128, true,true,false><<<gf1, 256>>>(xa, w1, bb1, nullptr, ffh, FF, HID);
        dim3 gf2((HID + 127) / 128, MB);
        gemm_tc<128, false,true,true><<<gf2, 256>>>(ffh, w2, bb2, xa, tmp, HID, FF);
        ln_kernel<true><<<ROWS/8, 256>>>(tmp, outb, g2 + l, be2 + l, acc);
    }

    seqsum1<<<dim3(BATCH, 8), 320>>>(outb, part);
    seqsum2<<<BATCH, 320>>>(part, sums);
    classify_kernel<<<dim3((NC + 255) / 256, BATCH), 256>>>(sums, Vd, logits);
    final_kernel<<<BATCH, 256>>>(logits, gf, bf, outp);
}

// round 8
// speedup vs baseline: 1.1564x; 1.1564x over previous
#include <cuda_runtime.h>
#include <math.h>

#define SEQ   512
#define BATCH 32
#define ROWS  16384        // BATCH*SEQ
#define HID   300
#define HDIM  64
#define NH    8
#define DH    8
#define NL    6
#define FF    1200
#define NC    1000

// ---------------- scratch (static device globals; no allocation) ----------------
__device__ float g_acc [ROWS*HID];
__device__ float g_out [ROWS*HID];
__device__ float g_xa  [ROWS*HID];
__device__ float g_tmp [ROWS*HID];
__device__ float g_qh  [ROWS*HDIM];
__device__ float g_kh  [ROWS*HDIM];
__device__ float g_vh  [ROWS*HDIM];
__device__ float g_attn[ROWS*HDIM];
__device__ float g_ffh [ROWS*FF];
__device__ float g_pe  [SEQ*HID];
__device__ float g_part[8*BATCH*HID];
__device__ float g_sums[BATCH*HID];
__device__ float g_logits[BATCH*NC];

// ---------------- positional encoding table ----------------
__global__ void pe_kernel(float* __restrict__ pe) {
    int s = blockIdx.x;
    for (int c = threadIdx.x; c < HID; c += blockDim.x) {
        double expo = (double)(c & ~1) / (double)HID;
        double ang  = (double)s * exp(-expo * 9.210340371976182736); // ln(10000)
        pe[s*HID + c] = (c & 1) ? (float)cos(ang) : (float)sin(ang);
    }
}

// acc = 2*emb[token] + PE   (x2 = emb+PE; acc = x2 + x1)
__global__ void embed_kernel(const int* __restrict__ tok,
                             const float* __restrict__ emb,
                             const float* __restrict__ pe,
                             float* __restrict__ accb) {
    int row = blockIdx.x;
    int s   = row & (SEQ - 1);
    long long t = tok[row];
    const float* er = emb + t * HID;
    const float* pr = pe + s * HID;
    for (int c = threadIdx.x; c < HID; c += blockDim.x) {
        accb[row*HID + c] = 2.f * er[c] + pr[c];
    }
}

// ================= tf32 tensor-core GEMM, cp.async double-buffered =================

__device__ __forceinline__ void mma_tf32(float d[4], const unsigned a[4],
                                         const unsigned b[2], const float c[4]) {
    asm volatile(
        "mma.sync.aligned.m16n8k8.row.col.f32.tf32.tf32.f32 "
        "{%0,%1,%2,%3}, {%4,%5,%6,%7}, {%8,%9}, {%10,%11,%12,%13};\n"
        : "=f"(d[0]), "=f"(d[1]), "=f"(d[2]), "=f"(d[3])
        : "r"(a[0]), "r"(a[1]), "r"(a[2]), "r"(a[3]),
          "r"(b[0]), "r"(b[1]),
          "f"(c[0]), "f"(c[1]), "f"(c[2]), "f"(c[3]));
}

__device__ __forceinline__ void cp16(void* smem, const void* gmem) {
    unsigned saddr = (unsigned)__cvta_generic_to_shared(smem);
    asm volatile("cp.async.cg.shared.global [%0], [%1], 16;" :: "r"(saddr), "l"(gmem));
}

#define AS_LD 20    // 128x16 A tile, m-major rows padded to 20 floats

// HM: head-major scatter store for QKV outputs (N==64, col = d*8+h)
template<int BN, bool RELU, bool BIAS, bool RES, bool HM>
__device__ __forceinline__ void gemm_body(const float* __restrict__ A,
                                          const float* __restrict__ B,
                                          const float* __restrict__ bias,
                                          const float* __restrict__ res,
                                          float* __restrict__ C,
                                          int N, int K, int bm, int bn) {
    constexpr int BS_LD = BN + 8;     // %32 == 8 -> conflict-free
    constexpr int NT = BN / 16;       // n-tiles of 8 per warp
    __shared__ float As[2][128][AS_LD];
    __shared__ float Bs[2][16][BS_LD];

    const int tid  = threadIdx.x;
    const int lane = tid & 31, warp = tid >> 5;
    const int gid  = lane >> 2, tig = lane & 3;
    const int rowb = (warp & 3) * 32;          // 4 warps over M
    const int nb   = (warp >> 2) * (BN / 2);   // 2 warps over N

    float acc[2][NT][4];
#pragma unroll
    for (int mt = 0; mt < 2; mt++)
#pragma unroll
        for (int nt = 0; nt < NT; nt++)
#pragma unroll
            for (int i = 0; i < 4; i++) acc[mt][nt][i] = 0.f;

    const int S = (K + 15) / 16;

    auto issue = [&](int s, int buf) {
        int k0 = s * 16;
#pragma unroll
        for (int j = 0; j < 2; j++) {
            int idx = tid + j * 256;
            int r = idx >> 2, c4 = (idx & 3) * 4;
            float* dst = &As[buf][r][c4];
            if (k0 + c4 < K) cp16(dst, A + (size_t)(bm + r) * K + k0 + c4);
            else *(float4*)dst = make_float4(0.f, 0.f, 0.f, 0.f);
        }
#pragma unroll
        for (int j = 0; j < BN / 64; j++) {
            int idx = tid + j * 256;
            int r = idx / (BN / 4);
            int c4 = (idx % (BN / 4)) * 4;
            float* dst = &Bs[buf][r][c4];
            int gr = k0 + r, gc = bn + c4;
            if (gr < K && gc < N) cp16(dst, B + (size_t)gr * N + gc);
            else *(float4*)dst = make_float4(0.f, 0.f, 0.f, 0.f);
        }
        asm volatile("cp.async.commit_group;");
    };

    issue(0, 0);

    for (int s = 0; s < S; s++) {
        asm volatile("cp.async.wait_group 0;");
        __syncthreads();
        if (s + 1 < S) issue(s + 1, (s + 1) & 1);

        const float (*as)[AS_LD] = As[s & 1];
        const float (*bs)[BS_LD] = Bs[s & 1];
#pragma unroll
        for (int ks = 0; ks < 2; ks++) {
            const int kk = ks * 8;
            unsigned af[2][4], bf[NT][2];
#pragma unroll
            for (int mt = 0; mt < 2; mt++) {
                int r0 = rowb + mt * 16 + gid;
                af[mt][0] = __float_as_uint(as[r0    ][kk + tig    ]);
                af[mt][1] = __float_as_uint(as[r0 + 8][kk + tig    ]);
                af[mt][2] = __float_as_uint(as[r0    ][kk + tig + 4]);
                af[mt][3] = __float_as_uint(as[r0 + 8][kk + tig + 4]);
            }
#pragma unroll
            for (int nt = 0; nt < NT; nt++) {
                int c0 = nb + nt * 8 + gid;
                bf[nt][0] = __float_as_uint(bs[kk + tig    ][c0]);
                bf[nt][1] = __float_as_uint(bs[kk + tig + 4][c0]);
            }
#pragma unroll
            for (int mt = 0; mt < 2; mt++)
#pragma unroll
                for (int nt = 0; nt < NT; nt++)
                    mma_tf32(acc[mt][nt], af[mt], bf[nt], acc[mt][nt]);
        }
    }

    // epilogue
#pragma unroll
    for (int mt = 0; mt < 2; mt++) {
        int row0 = bm + rowb + mt * 16 + gid;
#pragma unroll
        for (int nt = 0; nt < NT; nt++) {
            int col = bn + nb + nt * 8 + 2 * tig;
#pragma unroll
            for (int half = 0; half < 2; half++) {
                int row = row0 + half * 8;
                float v0 = acc[mt][nt][half * 2 + 0];
                float v1 = acc[mt][nt][half * 2 + 1];
                if (HM) {
                    // head-major: out[((col&7)*ROWS + row)*8 + (col>>3)]
                    C[(((size_t)(col & 7)) * ROWS + row) * 8 + (col >> 3)] = v0;
                    C[(((size_t)((col + 1) & 7)) * ROWS + row) * 8 + ((col + 1) >> 3)] = v1;
                } else {
                    if (col < N) {
                        if (BIAS) v0 += bias[col];
                        if (RES)  v0 += res[(size_t)row * N + col];
                        if (RELU) v0 = fmaxf(v0, 0.f);
                        C[(size_t)row * N + col] = v0;
                    }
                    if (col + 1 < N) {
                        if (BIAS) v1 += bias[col + 1];
                        if (RES)  v1 += res[(size_t)row * N + col + 1];
                        if (RELU) v1 = fmaxf(v1, 0.f);
                        C[(size_t)row * N + col + 1] = v1;
                    }
                }
            }
        }
    }
}

template<int BN, bool RELU, bool BIAS, bool RES>
__global__ void __launch_bounds__(256) gemm_tc(const float* __restrict__ A,
                                               const float* __restrict__ B,
                                               const float* __restrict__ bias,
                                               const float* __restrict__ res,
                                               float* __restrict__ C,
                                               int N, int K) {
    gemm_body<BN, RELU, BIAS, RES, false>(A, B, bias, res, C, N, K,
                                          blockIdx.y * 128, blockIdx.x * BN);
}

// fused QKV with head-major output: grid (1, M/128, 3)
__global__ void __launch_bounds__(256) qkv_tc(const float* __restrict__ A,
                                              const float* __restrict__ WQa,
                                              const float* __restrict__ WKa,
                                              const float* __restrict__ WVa,
                                              float* __restrict__ Qh,
                                              float* __restrict__ Kh,
                                              float* __restrict__ Vh) {
    const float* B = (blockIdx.z == 0) ? WQa : (blockIdx.z == 1) ? WKa : WVa;
    float* C = (blockIdx.z == 0) ? Qh : (blockIdx.z == 1) ? Kh : Vh;
    gemm_body<64, false, false, false, true>(A, B, nullptr, nullptr, C, HDIM, HID,
                                             blockIdx.y * 128, 0);
}

// ---------------- attention: head-major inputs, 2 queries/thread ----------------
// grid (NH, BATCH), 256 threads; thread handles queries tid and tid+256
__global__ void __launch_bounds__(256) attn_kernel(const float* __restrict__ Qh,
                                                   const float* __restrict__ Kh,
                                                   const float* __restrict__ Vh,
                                                   const int* __restrict__ tok,
                                                   float* __restrict__ O) {
    const int h = blockIdx.x;
    const int b = blockIdx.y;
    const int base = b * SEQ;
    __shared__ float Ks[SEQ][8];
    __shared__ float Vs[SEQ][8];
    __shared__ float mmul[SEQ];
    const int tid = threadIdx.x;

    const float4* kp = (const float4*)(Kh + ((size_t)h * ROWS + base) * 8);
    const float4* vp = (const float4*)(Vh + ((size_t)h * ROWS + base) * 8);
    float4* Ks4 = (float4*)Ks;
    float4* Vs4 = (float4*)Vs;
#pragma unroll
    for (int i = 0; i < 4; i++) {
        int idx = tid + i * 256;       // 1024 float4 per tensor
        Ks4[idx] = kp[idx];
        Vs4[idx] = vp[idx];
    }
#pragma unroll
    for (int i = 0; i < 2; i++) {
        int idx = tid + i * 256;
        mmul[idx] = (tok[base + idx] == 0) ? 0.f : 1.f;
    }
    __syncthreads();

    const float scale = 0.05773502691896258f; // 1/sqrt(300)
    float qa[8], qb[8];
    {
        const float* qp = Qh + ((size_t)h * ROWS + base + tid) * 8;
        float4 x0 = *(const float4*)qp;
        float4 x1 = *(const float4*)(qp + 4);
        qa[0]=x0.x*scale; qa[1]=x0.y*scale; qa[2]=x0.z*scale; qa[3]=x0.w*scale;
        qa[4]=x1.x*scale; qa[5]=x1.y*scale; qa[6]=x1.z*scale; qa[7]=x1.w*scale;
        const float* qp2 = qp + 256 * 8;
        float4 y0 = *(const float4*)qp2;
        float4 y1 = *(const float4*)(qp2 + 4);
        qb[0]=y0.x*scale; qb[1]=y0.y*scale; qb[2]=y0.z*scale; qb[3]=y0.w*scale;
        qb[4]=y1.x*scale; qb[5]=y1.y*scale; qb[6]=y1.z*scale; qb[7]=y1.w*scale;
    }

    float sa = 0.f, sb = 0.f, oa[8], ob[8];
#pragma unroll
    for (int d = 0; d < 8; d++) { oa[d] = 0.f; ob[d] = 0.f; }

#pragma unroll 2
    for (int k = 0; k < SEQ; k++) {
        float4 k0 = *(const float4*)&Ks[k][0];
        float4 k1 = *(const float4*)&Ks[k][4];
        float m = mmul[k];
        float da = qa[0]*k0.x + qa[1]*k0.y + qa[2]*k0.z + qa[3]*k0.w
                 + qa[4]*k1.x + qa[5]*k1.y + qa[6]*k1.z + qa[7]*k1.w;
        float db = qb[0]*k0.x + qb[1]*k0.y + qb[2]*k0.z + qb[3]*k0.w
                 + qb[4]*k1.x + qb[5]*k1.y + qb[6]*k1.z + qb[7]*k1.w;
        float pa = __expf(da) * m;
        float pb = __expf(db) * m;
        sa += pa; sb += pb;
        float4 v0 = *(const float4*)&Vs[k][0];
        float4 v1 = *(const float4*)&Vs[k][4];
        oa[0] += pa * v0.x; oa[1] += pa * v0.y; oa[2] += pa * v0.z; oa[3] += pa * v0.w;
        oa[4] += pa * v1.x; oa[5] += pa * v1.y; oa[6] += pa * v1.z; oa[7] += pa * v1.w;
        ob[0] += pb * v0.x; ob[1] += pb * v0.y; ob[2] += pb * v0.z; ob[3] += pb * v0.w;
        ob[4] += pb * v1.x; ob[5] += pb * v1.y; ob[6] += pb * v1.z; ob[7] += pb * v1.w;
    }

    {
        float inv = 1.f / sa;
        float* op = O + (size_t)(base + tid) * HDIM + h * 8;
        *(float4*)op       = make_float4(oa[0]*inv, oa[1]*inv, oa[2]*inv, oa[3]*inv);
        *(float4*)(op + 4) = make_float4(oa[4]*inv, oa[5]*inv, oa[6]*inv, oa[7]*inv);
    }
    {
        float inv = 1.f / sb;
        float* op = O + (size_t)(base + tid + 256) * HDIM + h * 8;
        *(float4*)op       = make_float4(ob[0]*inv, ob[1]*inv, ob[2]*inv, ob[3]*inv);
        *(float4*)(op + 4) = make_float4(ob[4]*inv, ob[5]*inv, ob[6]*inv, ob[7]*inv);
    }
}

// ---------------- LayerNorm: warp per row, shuffle reductions ----------------
template<bool ACC>
__global__ void __launch_bounds__(256) ln_kernel(const float* __restrict__ in,
                                                 float* __restrict__ outp,
                                                 const float* __restrict__ g,
                                                 const float* __restrict__ bt,
                                                 float* __restrict__ accb) {
    const int warp = threadIdx.x >> 5, lane = threadIdx.x & 31;
    const int row = blockIdx.x * 8 + warp;
    const float* x = in + (size_t)row * HID;

    float v[10];
    float s = 0.f;
#pragma unroll
    for (int i = 0; i < 10; i++) {
        int c = lane + i * 32;
        v[i] = (c < HID) ? x[c] : 0.f;
        s += v[i];
    }
#pragma unroll
    for (int o = 16; o; o >>= 1) s += __shfl_xor_sync(0xffffffffu, s, o);
    float mu = s / HID;

    float sq = 0.f;
#pragma unroll
    for (int i = 0; i < 10; i++) {
        int c = lane + i * 32;
        if (c < HID) { float d = v[i] - mu; sq += d * d; }
    }
#pragma unroll
    for (int o = 16; o; o >>= 1) sq += __shfl_xor_sync(0xffffffffu, sq, o);
    float inv = rsqrtf(sq / (HID - 1) + 1e-8f);

    float gg = g[0], bb = bt[0];
#pragma unroll
    for (int i = 0; i < 10; i++) {
        int c = lane + i * 32;
        if (c < HID) {
            float y = gg * (v[i] - mu) * inv + bb;
            outp[(size_t)row * HID + c] = y;
            if (ACC) accb[(size_t)row * HID + c] += y;
        }
    }
}

// ---------------- sum over sequence, two-stage (deterministic) ----------------
__global__ void seqsum1(const float* __restrict__ in, float* __restrict__ part) {
    int b = blockIdx.x, ch = blockIdx.y, c = threadIdx.x;
    if (c < HID) {
        float a = 0.f;
        const float* p = in + ((size_t)b * SEQ + ch * 64) * HID + c;
        for (int s = 0; s < 64; s++) a += p[(size_t)s * HID];
        part[((size_t)ch * BATCH + b) * HID + c] = a;
    }
}
__global__ void seqsum2(const float* __restrict__ part, float* __restrict__ sums) {
    int b = blockIdx.x, c = threadIdx.x;
    if (c < HID) {
        float a = 0.f;
#pragma unroll
        for (int ch = 0; ch < 8; ch++) a += part[((size_t)ch * BATCH + b) * HID + c];
        sums[b * HID + c] = a;
    }
}

// ---------------- classifier: (B,HID) @ (HID,NC) ----------------
__global__ void classify_kernel(const float* __restrict__ sums, const float* __restrict__ Vd,
                                float* __restrict__ logits) {
    int b = blockIdx.y;
    int c = blockIdx.x * 256 + threadIdx.x;
    __shared__ float srow[HID];
    for (int i = threadIdx.x; i < HID; i += 256) srow[i] = sums[b * HID + i];
    __syncthreads();
    if (c < NC) {
        float a = 0.f;
        for (int k = 0; k < HID; k++) a += srow[k] * Vd[(size_t)k * NC + c];
        logits[b * NC + c] = a;
    }
}

// ---------------- final LN (ddof=1) + softmax over NC ----------------
__global__ void final_kernel(const float* __restrict__ logits,
                             const float* __restrict__ gf, const float* __restrict__ bf,
                             float* __restrict__ outp) {
    const int b = blockIdx.x;
    const int t = threadIdx.x;   // 256
    __shared__ float buf[NC];
    __shared__ float red[256];
    const float* x = logits + (size_t)b * NC;

    float s = 0.f;
    for (int c = t; c < NC; c += 256) { float v = x[c]; buf[c] = v; s += v; }
    red[t] = s; __syncthreads();
    for (int st = 128; st > 0; st >>= 1) { if (t < st) red[t] += red[t + st]; __syncthreads(); }
    float mu = red[0] / NC;
    __syncthreads();

    float sq = 0.f;
    for (int c = t; c < NC; c += 256) { float d = buf[c] - mu; sq += d * d; }
    red[t] = sq; __syncthreads();
    for (int st = 128; st > 0; st >>= 1) { if (t < st) red[t] += red[t + st]; __syncthreads(); }
    float inv = rsqrtf(red[0] / (NC - 1) + 1e-8f);
    float gg = gf[0], bb = bf[0];
    __syncthreads();

    for (int c = t; c < NC; c += 256) buf[c] = gg * (buf[c] - mu) * inv + bb;
    __syncthreads();

    float mx = -1e30f;
    for (int c = t; c < NC; c += 256) mx = fmaxf(mx, buf[c]);
    red[t] = mx; __syncthreads();
    for (int st = 128; st > 0; st >>= 1) { if (t < st) red[t] = fmaxf(red[t], red[t + st]); __syncthreads(); }
    float rmax = red[0];
    __syncthreads();

    float es = 0.f;
    for (int c = t; c < NC; c += 256) es += __expf(buf[c] - rmax);
    red[t] = es; __syncthreads();
    for (int st = 128; st > 0; st >>= 1) { if (t < st) red[t] += red[t + st]; __syncthreads(); }
    float invs = 1.f / red[0];
    __syncthreads();

    for (int c = t; c < NC; c += 256) outp[(size_t)b * NC + c] = __expf(buf[c] - rmax) * invs;
}

// ---------------- launch ----------------
extern "C" void kernel_launch(void* const* d_in, const int* in_sizes, int n_in,
                              void* d_out, int out_size) {
    const int*   xk  = (const int*)  d_in[0];
    const float* emb = (const float*)d_in[1];
    const float* WQ  = (const float*)d_in[2];
    const float* WK  = (const float*)d_in[3];
    const float* WV  = (const float*)d_in[4];
    const float* WO  = (const float*)d_in[5];
    const float* W1  = (const float*)d_in[6];
    const float* b1  = (const float*)d_in[7];
    const float* W2  = (const float*)d_in[8];
    const float* b2  = (const float*)d_in[9];
    const float* g1  = (const float*)d_in[10];
    const float* be1 = (const float*)d_in[11];
    const float* g2  = (const float*)d_in[12];
    const float* be2 = (const float*)d_in[13];
    const float* Vd  = (const float*)d_in[14];
    const float* gf  = (const float*)d_in[15];
    const float* bf  = (const float*)d_in[16];
    float* outp = (float*)d_out;

    float *acc, *outb, *xa, *tmp, *qh, *kh, *vh, *attn, *ffh, *pe, *part, *sums, *logits;
    cudaGetSymbolAddress((void**)&acc,   g_acc);
    cudaGetSymbolAddress((void**)&outb,  g_out);
    cudaGetSymbolAddress((void**)&xa,    g_xa);
    cudaGetSymbolAddress((void**)&tmp,   g_tmp);
    cudaGetSymbolAddress((void**)&qh,    g_qh);
    cudaGetSymbolAddress((void**)&kh,    g_kh);
    cudaGetSymbolAddress((void**)&vh,    g_vh);
    cudaGetSymbolAddress((void**)&attn,  g_attn);
    cudaGetSymbolAddress((void**)&ffh,   g_ffh);
    cudaGetSymbolAddress((void**)&pe,    g_pe);
    cudaGetSymbolAddress((void**)&part,  g_part);
    cudaGetSymbolAddress((void**)&sums,  g_sums);
    cudaGetSymbolAddress((void**)&logits,g_logits);

    pe_kernel<<<SEQ, 128>>>(pe);
    embed_kernel<<<ROWS, 128>>>(xk, emb, pe, acc);

    const int MB = ROWS / 128;   // 128 m-blocks

    for (int l = 0; l < NL; l++) {
        const float* wq = WQ + (size_t)l * HID * HDIM;
        const float* wk = WK + (size_t)l * HID * HDIM;
        const float* wv = WV + (size_t)l * HID * HDIM;
        const float* wo = WO + (size_t)l * HDIM * HID;
        const float* w1 = W1 + (size_t)l * HID * FF;
        const float* w2 = W2 + (size_t)l * FF * HID;
        const float* bb1 = b1 + (size_t)l * FF;
        const float* bb2 = b2 + (size_t)l * HID;

        qkv_tc<<<dim3(1, MB, 3), 256>>>(acc, wq, wk, wv, qh, kh, vh);

        attn_kernel<<<dim3(NH, BATCH), 256>>>(qh, kh, vh, xk, attn);

        dim3 go((HID + 63) / 64, MB);
        gemm_tc<64, false,false,true><<<go, 256>>>(attn, wo, nullptr, acc, tmp, HID, HDIM);
        ln_kernel<false><<<ROWS/8, 256>>>(tmp, xa, g1 + l, be1 + l, nullptr);

        dim3 gf1((FF + 127) / 128, MB);
        gemm_tc<128, true,true,false><<<gf1, 256>>>(xa, w1, bb1, nullptr, ffh, FF, HID);
        gemm_tc<64, false,true,true><<<go, 256>>>(ffh, w2, bb2, xa, tmp, HID, FF);
        ln_kernel<true><<<ROWS/8, 256>>>(tmp, outb, g2 + l, be2 + l, acc);
    }

    seqsum1<<<dim3(BATCH, 8), 320>>>(outb, part);
    seqsum2<<<BATCH, 320>>>(part, sums);
    classify_kernel<<<dim3((NC + 255) / 256, BATCH), 256>>>(sums, Vd, logits);
    final_kernel<<<BATCH, 256>>>(logits, gf, bf, outp);
}

// round 9
// speedup vs baseline: 1.1722x; 1.0136x over previous
#include <cuda_runtime.h>
#include <math.h>

#define SEQ   512
#define BATCH 32
#define ROWS  16384        // BATCH*SEQ
#define HID   300
#define HDIM  64
#define NH    8
#define DH    8
#define NL    6
#define FF    1200
#define NC    1000

// ---------------- scratch (static device globals; no allocation) ----------------
__device__ float g_acc [ROWS*HID];
__device__ float g_out [ROWS*HID];
__device__ float g_xa  [ROWS*HID];
__device__ float g_tmp [ROWS*HID];
__device__ float g_qh  [ROWS*HDIM];
__device__ float g_kh  [ROWS*HDIM];
__device__ float g_vh  [ROWS*HDIM];
__device__ float g_attn[ROWS*HDIM];
__device__ float g_ffh [ROWS*FF];
__device__ float g_pe  [SEQ*HID];
__device__ float g_part[8*BATCH*HID];
__device__ float g_sums[BATCH*HID];
__device__ float g_logits[BATCH*NC];

// ---------------- positional encoding table ----------------
__global__ void pe_kernel(float* __restrict__ pe) {
    int s = blockIdx.x;
    for (int c = threadIdx.x; c < HID; c += blockDim.x) {
        double expo = (double)(c & ~1) / (double)HID;
        double ang  = (double)s * exp(-expo * 9.210340371976182736); // ln(10000)
        pe[s*HID + c] = (c & 1) ? (float)cos(ang) : (float)sin(ang);
    }
}

// acc = 2*emb[token] + PE   (x2 = emb+PE; acc = x2 + x1)
__global__ void embed_kernel(const int* __restrict__ tok,
                             const float* __restrict__ emb,
                             const float* __restrict__ pe,
                             float* __restrict__ accb) {
    int row = blockIdx.x;
    int s   = row & (SEQ - 1);
    long long t = tok[row];
    const float* er = emb + t * HID;
    const float* pr = pe + s * HID;
    for (int c = threadIdx.x; c < HID; c += blockDim.x) {
        accb[row*HID + c] = 2.f * er[c] + pr[c];
    }
}

// ================= tf32 tensor-core GEMM, 3-stage cp.async pipeline =================

__device__ __forceinline__ void mma_tf32(float d[4], const unsigned a[4],
                                         const unsigned b[2], const float c[4]) {
    asm volatile(
        "mma.sync.aligned.m16n8k8.row.col.f32.tf32.tf32.f32 "
        "{%0,%1,%2,%3}, {%4,%5,%6,%7}, {%8,%9}, {%10,%11,%12,%13};\n"
        : "=f"(d[0]), "=f"(d[1]), "=f"(d[2]), "=f"(d[3])
        : "r"(a[0]), "r"(a[1]), "r"(a[2]), "r"(a[3]),
          "r"(b[0]), "r"(b[1]),
          "f"(c[0]), "f"(c[1]), "f"(c[2]), "f"(c[3]));
}

__device__ __forceinline__ void cp16(void* smem, const void* gmem) {
    unsigned saddr = (unsigned)__cvta_generic_to_shared(smem);
    asm volatile("cp.async.cg.shared.global [%0], [%1], 16;" :: "r"(saddr), "l"(gmem));
}

#define AS_LD 20    // 128x16 A tile, m-major rows padded to 20 floats
#define NSTAGE 3

// HM: head-major scatter store for QKV outputs (N==64, col = d*8+h)
template<int BN, bool RELU, bool BIAS, bool RES, bool HM>
__device__ __forceinline__ void gemm_body(const float* __restrict__ A,
                                          const float* __restrict__ B,
                                          const float* __restrict__ bias,
                                          const float* __restrict__ res,
                                          float* __restrict__ C,
                                          int N, int K, int bm, int bn) {
    constexpr int BS_LD = BN + 8;     // %32 == 8 -> conflict-free
    constexpr int NT = BN / 16;       // n-tiles of 8 per warp
    extern __shared__ float dsm[];
    float (*As)[128][AS_LD] = (float (*)[128][AS_LD])dsm;
    float (*Bs)[16][BS_LD]  = (float (*)[16][BS_LD])(dsm + NSTAGE * 128 * AS_LD);

    const int tid  = threadIdx.x;
    const int lane = tid & 31, warp = tid >> 5;
    const int gid  = lane >> 2, tig = lane & 3;
    const int rowb = (warp & 3) * 32;          // 4 warps over M
    const int nb   = (warp >> 2) * (BN / 2);   // 2 warps over N

    float acc[2][NT][4];
#pragma unroll
    for (int mt = 0; mt < 2; mt++)
#pragma unroll
        for (int nt = 0; nt < NT; nt++)
#pragma unroll
            for (int i = 0; i < 4; i++) acc[mt][nt][i] = 0.f;

    const int S = (K + 15) / 16;

    auto issue = [&](int s) {
        int buf = s % NSTAGE;
        int k0 = s * 16;
#pragma unroll
        for (int j = 0; j < 2; j++) {
            int idx = tid + j * 256;
            int r = idx >> 2, c4 = (idx & 3) * 4;
            float* dst = &As[buf][r][c4];
            if (k0 + c4 < K) cp16(dst, A + (size_t)(bm + r) * K + k0 + c4);
            else *(float4*)dst = make_float4(0.f, 0.f, 0.f, 0.f);
        }
#pragma unroll
        for (int j = 0; j < BN / 64; j++) {
            int idx = tid + j * 256;
            int r = idx / (BN / 4);
            int c4 = (idx % (BN / 4)) * 4;
            float* dst = &Bs[buf][r][c4];
            int gr = k0 + r, gc = bn + c4;
            if (gr < K && gc < N) cp16(dst, B + (size_t)gr * N + gc);
            else *(float4*)dst = make_float4(0.f, 0.f, 0.f, 0.f);
        }
        asm volatile("cp.async.commit_group;");
    };

    issue(0);
    if (S > 1) issue(1);

    for (int s = 0; s < S; s++) {
        if (s + 1 < S) asm volatile("cp.async.wait_group 1;");
        else           asm volatile("cp.async.wait_group 0;");
        __syncthreads();
        if (s + 2 < S) issue(s + 2);

        const float (*as)[AS_LD] = As[s % NSTAGE];
        const float (*bs)[BS_LD] = Bs[s % NSTAGE];
#pragma unroll
        for (int ks = 0; ks < 2; ks++) {
            const int kk = ks * 8;
            unsigned af[2][4], bf[NT][2];
#pragma unroll
            for (int mt = 0; mt < 2; mt++) {
                int r0 = rowb + mt * 16 + gid;
                af[mt][0] = __float_as_uint(as[r0    ][kk + tig    ]);
                af[mt][1] = __float_as_uint(as[r0 + 8][kk + tig    ]);
                af[mt][2] = __float_as_uint(as[r0    ][kk + tig + 4]);
                af[mt][3] = __float_as_uint(as[r0 + 8][kk + tig + 4]);
            }
#pragma unroll
            for (int nt = 0; nt < NT; nt++) {
                int c0 = nb + nt * 8 + gid;
                bf[nt][0] = __float_as_uint(bs[kk + tig    ][c0]);
                bf[nt][1] = __float_as_uint(bs[kk + tig + 4][c0]);
            }
#pragma unroll
            for (int mt = 0; mt < 2; mt++)
#pragma unroll
                for (int nt = 0; nt < NT; nt++)
                    mma_tf32(acc[mt][nt], af[mt], bf[nt], acc[mt][nt]);
        }
    }

    // epilogue
#pragma unroll
    for (int mt = 0; mt < 2; mt++) {
        int row0 = bm + rowb + mt * 16 + gid;
#pragma unroll
        for (int nt = 0; nt < NT; nt++) {
            int col = bn + nb + nt * 8 + 2 * tig;
#pragma unroll
            for (int half = 0; half < 2; half++) {
                int row = row0 + half * 8;
                float v0 = acc[mt][nt][half * 2 + 0];
                float v1 = acc[mt][nt][half * 2 + 1];
                if (HM) {
                    C[(((size_t)(col & 7)) * ROWS + row) * 8 + (col >> 3)] = v0;
                    C[(((size_t)((col + 1) & 7)) * ROWS + row) * 8 + ((col + 1) >> 3)] = v1;
                } else {
                    if (col < N) {
                        if (BIAS) v0 += bias[col];
                        if (RES)  v0 += res[(size_t)row * N + col];
                        if (RELU) v0 = fmaxf(v0, 0.f);
                        C[(size_t)row * N + col] = v0;
                    }
                    if (col + 1 < N) {
                        if (BIAS) v1 += bias[col + 1];
                        if (RES)  v1 += res[(size_t)row * N + col + 1];
                        if (RELU) v1 = fmaxf(v1, 0.f);
                        C[(size_t)row * N + col + 1] = v1;
                    }
                }
            }
        }
    }
}

template<int BN, bool RELU, bool BIAS, bool RES>
__global__ void __launch_bounds__(256) gemm_tc(const float* __restrict__ A,
                                               const float* __restrict__ B,
                                               const float* __restrict__ bias,
                                               const float* __restrict__ res,
                                               float* __restrict__ C,
                                               int N, int K) {
    gemm_body<BN, RELU, BIAS, RES, false>(A, B, bias, res, C, N, K,
                                          blockIdx.y * 128, blockIdx.x * BN);
}

// fused QKV with head-major output: grid (1, M/128, 3)
__global__ void __launch_bounds__(256) qkv_tc(const float* __restrict__ A,
                                              const float* __restrict__ WQa,
                                              const float* __restrict__ WKa,
                                              const float* __restrict__ WVa,
                                              float* __restrict__ Qh,
                                              float* __restrict__ Kh,
                                              float* __restrict__ Vh) {
    const float* B = (blockIdx.z == 0) ? WQa : (blockIdx.z == 1) ? WKa : WVa;
    float* C = (blockIdx.z == 0) ? Qh : (blockIdx.z == 1) ? Kh : Vh;
    gemm_body<64, false, false, false, true>(A, B, nullptr, nullptr, C, HDIM, HID,
                                             blockIdx.y * 128, 0);
}

// smem byte sizes for the pipeline
#define SMEM_BN64  ((NSTAGE*128*AS_LD + NSTAGE*16*(64+8)) * 4)
#define SMEM_BN128 ((NSTAGE*128*AS_LD + NSTAGE*16*(128+8)) * 4)

// ---------------- attention: head-major inputs, 2 queries/thread ----------------
__global__ void __launch_bounds__(256) attn_kernel(const float* __restrict__ Qh,
                                                   const float* __restrict__ Kh,
                                                   const float* __restrict__ Vh,
                                                   const int* __restrict__ tok,
                                                   float* __restrict__ O) {
    const int h = blockIdx.x;
    const int b = blockIdx.y;
    const int base = b * SEQ;
    __shared__ float Ks[SEQ][8];
    __shared__ float Vs[SEQ][8];
    __shared__ float mmul[SEQ];
    const int tid = threadIdx.x;

    const float4* kp = (const float4*)(Kh + ((size_t)h * ROWS + base) * 8);
    const float4* vp = (const float4*)(Vh + ((size_t)h * ROWS + base) * 8);
    float4* Ks4 = (float4*)Ks;
    float4* Vs4 = (float4*)Vs;
#pragma unroll
    for (int i = 0; i < 4; i++) {
        int idx = tid + i * 256;       // 1024 float4 per tensor
        Ks4[idx] = kp[idx];
        Vs4[idx] = vp[idx];
    }
#pragma unroll
    for (int i = 0; i < 2; i++) {
        int idx = tid + i * 256;
        mmul[idx] = (tok[base + idx] == 0) ? 0.f : 1.f;
    }
    __syncthreads();

    const float scale = 0.05773502691896258f; // 1/sqrt(300)
    float qa[8], qb[8];
    {
        const float* qp = Qh + ((size_t)h * ROWS + base + tid) * 8;
        float4 x0 = *(const float4*)qp;
        float4 x1 = *(const float4*)(qp + 4);
        qa[0]=x0.x*scale; qa[1]=x0.y*scale; qa[2]=x0.z*scale; qa[3]=x0.w*scale;
        qa[4]=x1.x*scale; qa[5]=x1.y*scale; qa[6]=x1.z*scale; qa[7]=x1.w*scale;
        const float* qp2 = qp + 256 * 8;
        float4 y0 = *(const float4*)qp2;
        float4 y1 = *(const float4*)(qp2 + 4);
        qb[0]=y0.x*scale; qb[1]=y0.y*scale; qb[2]=y0.z*scale; qb[3]=y0.w*scale;
        qb[4]=y1.x*scale; qb[5]=y1.y*scale; qb[6]=y1.z*scale; qb[7]=y1.w*scale;
    }

    float sa = 0.f, sb = 0.f, oa[8], ob[8];
#pragma unroll
    for (int d = 0; d < 8; d++) { oa[d] = 0.f; ob[d] = 0.f; }

#pragma unroll 2
    for (int k = 0; k < SEQ; k++) {
        float4 k0 = *(const float4*)&Ks[k][0];
        float4 k1 = *(const float4*)&Ks[k][4];
        float m = mmul[k];
        float da = qa[0]*k0.x + qa[1]*k0.y + qa[2]*k0.z + qa[3]*k0.w
                 + qa[4]*k1.x + qa[5]*k1.y + qa[6]*k1.z + qa[7]*k1.w;
        float db = qb[0]*k0.x + qb[1]*k0.y + qb[2]*k0.z + qb[3]*k0.w
                 + qb[4]*k1.x + qb[5]*k1.y + qb[6]*k1.z + qb[7]*k1.w;
        float pa = __expf(da) * m;
        float pb = __expf(db) * m;
        sa += pa; sb += pb;
        float4 v0 = *(const float4*)&Vs[k][0];
        float4 v1 = *(const float4*)&Vs[k][4];
        oa[0] += pa * v0.x; oa[1] += pa * v0.y; oa[2] += pa * v0.z; oa[3] += pa * v0.w;
        oa[4] += pa * v1.x; oa[5] += pa * v1.y; oa[6] += pa * v1.z; oa[7] += pa * v1.w;
        ob[0] += pb * v0.x; ob[1] += pb * v0.y; ob[2] += pb * v0.z; ob[3] += pb * v0.w;
        ob[4] += pb * v1.x; ob[5] += pb * v1.y; ob[6] += pb * v1.z; ob[7] += pb * v1.w;
    }

    {
        float inv = 1.f / sa;
        float* op = O + (size_t)(base + tid) * HDIM + h * 8;
        *(float4*)op       = make_float4(oa[0]*inv, oa[1]*inv, oa[2]*inv, oa[3]*inv);
        *(float4*)(op + 4) = make_float4(oa[4]*inv, oa[5]*inv, oa[6]*inv, oa[7]*inv);
    }
    {
        float inv = 1.f / sb;
        float* op = O + (size_t)(base + tid + 256) * HDIM + h * 8;
        *(float4*)op       = make_float4(ob[0]*inv, ob[1]*inv, ob[2]*inv, ob[3]*inv);
        *(float4*)(op + 4) = make_float4(ob[4]*inv, ob[5]*inv, ob[6]*inv, ob[7]*inv);
    }
}

// ---------------- LayerNorm: warp per row, shuffle reductions ----------------
template<bool ACC>
__global__ void __launch_bounds__(256) ln_kernel(const float* __restrict__ in,
                                                 float* __restrict__ outp,
                                                 const float* __restrict__ g,
                                                 const float* __restrict__ bt,
                                                 float* __restrict__ accb) {
    const int warp = threadIdx.x >> 5, lane = threadIdx.x & 31;
    const int row = blockIdx.x * 8 + warp;
    const float* x = in + (size_t)row * HID;

    float v[10];
    float s = 0.f;
#pragma unroll
    for (int i = 0; i < 10; i++) {
        int c = lane + i * 32;
        v[i] = (c < HID) ? x[c] : 0.f;
        s += v[i];
    }
#pragma unroll
    for (int o = 16; o; o >>= 1) s += __shfl_xor_sync(0xffffffffu, s, o);
    float mu = s / HID;

    float sq = 0.f;
#pragma unroll
    for (int i = 0; i < 10; i++) {
        int c = lane + i * 32;
        if (c < HID) { float d = v[i] - mu; sq += d * d; }
    }
#pragma unroll
    for (int o = 16; o; o >>= 1) sq += __shfl_xor_sync(0xffffffffu, sq, o);
    float inv = rsqrtf(sq / (HID - 1) + 1e-8f);

    float gg = g[0], bb = bt[0];
#pragma unroll
    for (int i = 0; i < 10; i++) {
        int c = lane + i * 32;
        if (c < HID) {
            float y = gg * (v[i] - mu) * inv + bb;
            outp[(size_t)row * HID + c] = y;
            if (ACC) accb[(size_t)row * HID + c] += y;
        }
    }
}

// ---------------- sum over sequence, two-stage (deterministic) ----------------
__global__ void seqsum1(const float* __restrict__ in, float* __restrict__ part) {
    int b = blockIdx.x, ch = blockIdx.y, c = threadIdx.x;
    if (c < HID) {
        float a = 0.f;
        const float* p = in + ((size_t)b * SEQ + ch * 64) * HID + c;
        for (int s = 0; s < 64; s++) a += p[(size_t)s * HID];
        part[((size_t)ch * BATCH + b) * HID + c] = a;
    }
}
__global__ void seqsum2(const float* __restrict__ part, float* __restrict__ sums) {
    int b = blockIdx.x, c = threadIdx.x;
    if (c < HID) {
        float a = 0.f;
#pragma unroll
        for (int ch = 0; ch < 8; ch++) a += part[((size_t)ch * BATCH + b) * HID + c];
        sums[b * HID + c] = a;
    }
}

// ---------------- classifier: (B,HID) @ (HID,NC) ----------------
__global__ void classify_kernel(const float* __restrict__ sums, const float* __restrict__ Vd,
                                float* __restrict__ logits) {
    int b = blockIdx.y;
    int c = blockIdx.x * 256 + threadIdx.x;
    __shared__ float srow[HID];
    for (int i = threadIdx.x; i < HID; i += 256) srow[i] = sums[b * HID + i];
    __syncthreads();
    if (c < NC) {
        float a = 0.f;
        for (int k = 0; k < HID; k++) a += srow[k] * Vd[(size_t)k * NC + c];
        logits[b * NC + c] = a;
    }
}

// ---------------- final LN (ddof=1) + softmax over NC ----------------
__global__ void final_kernel(const float* __restrict__ logits,
                             const float* __restrict__ gf, const float* __restrict__ bf,
                             float* __restrict__ outp) {
    const int b = blockIdx.x;
    const int t = threadIdx.x;   // 256
    __shared__ float buf[NC];
    __shared__ float red[256];
    const float* x = logits + (size_t)b * NC;

    float s = 0.f;
    for (int c = t; c < NC; c += 256) { float v = x[c]; buf[c] = v; s += v; }
    red[t] = s; __syncthreads();
    for (int st = 128; st > 0; st >>= 1) { if (t < st) red[t] += red[t + st]; __syncthreads(); }
    float mu = red[0] / NC;
    __syncthreads();

    float sq = 0.f;
    for (int c = t; c < NC; c += 256) { float d = buf[c] - mu; sq += d * d; }
    red[t] = sq; __syncthreads();
    for (int st = 128; st > 0; st >>= 1) { if (t < st) red[t] += red[t + st]; __syncthreads(); }
    float inv = rsqrtf(red[0] / (NC - 1) + 1e-8f);
    float gg = gf[0], bb = bf[0];
    __syncthreads();

    for (int c = t; c < NC; c += 256) buf[c] = gg * (buf[c] - mu) * inv + bb;
    __syncthreads();

    float mx = -1e30f;
    for (int c = t; c < NC; c += 256) mx = fmaxf(mx, buf[c]);
    red[t] = mx; __syncthreads();
    for (int st = 128; st > 0; st >>= 1) { if (t < st) red[t] = fmaxf(red[t], red[t + st]); __syncthreads(); }
    float rmax = red[0];
    __syncthreads();

    float es = 0.f;
    for (int c = t; c < NC; c += 256) es += __expf(buf[c] - rmax);
    red[t] = es; __syncthreads();
    for (int st = 128; st > 0; st >>= 1) { if (t < st) red[t] += red[t + st]; __syncthreads(); }
    float invs = 1.f / red[0];
    __syncthreads();

    for (int c = t; c < NC; c += 256) outp[(size_t)b * NC + c] = __expf(buf[c] - rmax) * invs;
}

// ---------------- launch ----------------
extern "C" void kernel_launch(void* const* d_in, const int* in_sizes, int n_in,
                              void* d_out, int out_size) {
    const int*   xk  = (const int*)  d_in[0];
    const float* emb = (const float*)d_in[1];
    const float* WQ  = (const float*)d_in[2];
    const float* WK  = (const float*)d_in[3];
    const float* WV  = (const float*)d_in[4];
    const float* WO  = (const float*)d_in[5];
    const float* W1  = (const float*)d_in[6];
    const float* b1  = (const float*)d_in[7];
    const float* W2  = (const float*)d_in[8];
    const float* b2  = (const float*)d_in[9];
    const float* g1  = (const float*)d_in[10];
    const float* be1 = (const float*)d_in[11];
    const float* g2  = (const float*)d_in[12];
    const float* be2 = (const float*)d_in[13];
    const float* Vd  = (const float*)d_in[14];
    const float* gf  = (const float*)d_in[15];
    const float* bf  = (const float*)d_in[16];
    float* outp = (float*)d_out;

    float *acc, *outb, *xa, *tmp, *qh, *kh, *vh, *attn, *ffh, *pe, *part, *sums, *logits;
    cudaGetSymbolAddress((void**)&acc,   g_acc);
    cudaGetSymbolAddress((void**)&outb,  g_out);
    cudaGetSymbolAddress((void**)&xa,    g_xa);
    cudaGetSymbolAddress((void**)&tmp,   g_tmp);
    cudaGetSymbolAddress((void**)&qh,    g_qh);
    cudaGetSymbolAddress((void**)&kh,    g_kh);
    cudaGetSymbolAddress((void**)&vh,    g_vh);
    cudaGetSymbolAddress((void**)&attn,  g_attn);
    cudaGetSymbolAddress((void**)&ffh,   g_ffh);
    cudaGetSymbolAddress((void**)&pe,    g_pe);
    cudaGetSymbolAddress((void**)&part,  g_part);
    cudaGetSymbolAddress((void**)&sums,  g_sums);
    cudaGetSymbolAddress((void**)&logits,g_logits);

    // allow >48KB dynamic smem for the pipelined GEMMs (idempotent, capture-safe)
    static bool attr_done = false;
    if (!attr_done) {
        cudaFuncSetAttribute(qkv_tc, cudaFuncAttributeMaxDynamicSharedMemorySize, SMEM_BN64);
        cudaFuncSetAttribute(gemm_tc<64, false,false,true>,  cudaFuncAttributeMaxDynamicSharedMemorySize, SMEM_BN64);
        cudaFuncSetAttribute(gemm_tc<128, true,true,false>,  cudaFuncAttributeMaxDynamicSharedMemorySize, SMEM_BN128);
        cudaFuncSetAttribute(gemm_tc<64, false,true,true>,   cudaFuncAttributeMaxDynamicSharedMemorySize, SMEM_BN64);
        attr_done = true;
    }

    pe_kernel<<<SEQ, 128>>>(pe);
    embed_kernel<<<ROWS, 128>>>(xk, emb, pe, acc);

    const int MB = ROWS / 128;   // 128 m-blocks

    for (int l = 0; l < NL; l++) {
        const float* wq = WQ + (size_t)l * HID * HDIM;
        const float* wk = WK + (size_t)l * HID * HDIM;
        const float* wv = WV + (size_t)l * HID * HDIM;
        const float* wo = WO + (size_t)l * HDIM * HID;
        const float* w1 = W1 + (size_t)l * HID * FF;
        const float* w2 = W2 + (size_t)l * FF * HID;
        const float* bb1 = b1 + (size_t)l * FF;
        const float* bb2 = b2 + (size_t)l * HID;

        qkv_tc<<<dim3(1, MB, 3), 256, SMEM_BN64>>>(acc, wq, wk, wv, qh, kh, vh);

        attn_kernel<<<dim3(NH, BATCH), 256>>>(qh, kh, vh, xk, attn);

        dim3 go((HID + 63) / 64, MB);
        gemm_tc<64, false,false,true><<<go, 256, SMEM_BN64>>>(attn, wo, nullptr, acc, tmp, HID, HDIM);
        ln_kernel<false><<<ROWS/8, 256>>>(tmp, xa, g1 + l, be1 + l, nullptr);

        dim3 gf1((FF + 127) / 128, MB);
        gemm_tc<128, true,true,false><<<gf1, 256, SMEM_BN128>>>(xa, w1, bb1, nullptr, ffh, FF, HID);
        gemm_tc<64, false,true,true><<<go, 256, SMEM_BN64>>>(ffh, w2, bb2, xa, tmp, HID, FF);
        ln_kernel<true><<<ROWS/8, 256>>>(tmp, outb, g2 + l, be2 + l, acc);
    }

    seqsum1<<<dim3(BATCH, 8), 320>>>(outb, part);
    seqsum2<<<BATCH, 320>>>(part, sums);
    classify_kernel<<<dim3((NC + 255) / 256, BATCH), 256>>>(sums, Vd, logits);
    final_kernel<<<BATCH, 256>>>(logits, gf, bf, outp);
}